// round 1
// baseline (speedup 1.0000x reference)
#include <cuda_runtime.h>

// Problem geometry (fixed by the dataset):
//   y: [1,512,512,8,8] f32 = 16,777,216 elems
//   c: [2,256,256,8,8] f32 =  8,388,608 elems (2 channels x 4,194,304)
// Output: y then c concatenated, 25,165,824 f32.

#define CMIN  (-1024.0f)
#define CMAX  (1016.0f)
#define FACT  (1.9f)

static const long long NY      = 16777216LL;      // y elems
static const long long NC      = 8388608LL;       // c elems
static const long long NY4     = NY / 4;          // 4,194,304 float4
static const long long NC4     = NC / 4;          // 2,097,152 float4
static const int       N_DC    = 131072;          // 2 * 65536 DC coeffs
static const float     INV_CNT = 1.0f / 65536.0f;

__device__ float g_dc_sum[2];

__device__ __forceinline__ float clampf(float v) {
    return fminf(fmaxf(v, CMIN), CMAX);
}

__global__ void zero_acc_kernel() {
    if (threadIdx.x < 2) g_dc_sum[threadIdx.x] = 0.0f;
}

// 512 blocks x 256 threads, one DC coefficient per thread.
// DC coeff idx lives at c[idx * 64] (channel stride 65536*64 makes this global).
__global__ void dc_reduce_kernel(const float* __restrict__ c) {
    int idx = blockIdx.x * 256 + threadIdx.x;     // 0 .. 131071
    int ch  = idx >> 16;                          // constant per block (65536 % 256 == 0 per-ch)
    float v = clampf(c[(long long)idx * 64]);

    #pragma unroll
    for (int off = 16; off > 0; off >>= 1)
        v += __shfl_down_sync(0xffffffffu, v, off);

    __shared__ float s[8];
    if ((threadIdx.x & 31) == 0) s[threadIdx.x >> 5] = v;
    __syncthreads();
    if (threadIdx.x < 8) {
        float w = s[threadIdx.x];
        #pragma unroll
        for (int off = 4; off > 0; off >>= 1)
            w += __shfl_down_sync(0xffu, w, off);
        if (threadIdx.x == 0) atomicAdd(&g_dc_sum[ch], w);
    }
}

// One float4 per thread, exact grid. Blocks [0, NY4) handle y, rest handle c.
__global__ void __launch_bounds__(256) ew_kernel(
    const float4* __restrict__ y, const float4* __restrict__ c,
    float4* __restrict__ oy, float4* __restrict__ oc)
{
    long long i = (long long)blockIdx.x * 256 + threadIdx.x;
    if (i < NY4) {
        float4 v = y[i];
        v.x = clampf(clampf(v.x) * FACT);
        v.y = clampf(clampf(v.y) * FACT);
        v.z = clampf(clampf(v.z) * FACT);
        v.w = clampf(clampf(v.w) * FACT);
        oy[i] = v;
    } else {
        long long j = i - NY4;                    // 0 .. NC4-1
        float4 v = c[j];
        v.x = clampf(v.x) * FACT;
        v.y = clampf(v.y) * FACT;
        v.z = clampf(v.z) * FACT;
        v.w = clampf(v.w) * FACT;
        if ((j & 15) == 0) {                      // elem j*4 is a DC coeff (idx%64==0)
            int ch = (int)(j >> 20);              // j / 1,048,576 float4 per channel
            v.x += (1.0f - FACT) * (g_dc_sum[ch] * INV_CNT);
        }
        v.x = clampf(v.x);
        v.y = clampf(v.y);
        v.z = clampf(v.z);
        v.w = clampf(v.w);
        oc[j] = v;
    }
}

extern "C" void kernel_launch(void* const* d_in, const int* in_sizes, int n_in,
                              void* d_out, int out_size) {
    const float* y = (const float*)d_in[0];
    const float* c = (const float*)d_in[1];
    float* oy = (float*)d_out;
    float* oc = (float*)d_out + NY;

    zero_acc_kernel<<<1, 32>>>();
    dc_reduce_kernel<<<N_DC / 256, 256>>>(c);
    long long total4 = NY4 + NC4;                 // 6,291,456 -> 24,576 blocks
    ew_kernel<<<(unsigned)(total4 / 256), 256>>>(
        (const float4*)y, (const float4*)c, (float4*)oy, (float4*)oc);
}